// round 1
// baseline (speedup 1.0000x reference)
#include <cuda_runtime.h>
#include <math.h>

#define Bb   512
#define Hh   256
#define Ld   256
#define Tt   64
#define Vv   128
#define NL   2
#define G    4
#define NTH  256

// ---------------- packed weight scratch (transposed + k-interleaved) ----------------
// Layout P[(k4*N + j)*4 + c] = W[j*K + 4*k4 + c]  so a thread owning column j loads
// float4 = W[j][4k4..4k4+3] fully coalesced across threads.
#define OFF_ATTN 0          // 512x256  -> 131072 floats
#define OFF_COMB 131072     // 512x256  -> 131072
#define OFF_GIH  262144     // 2 x 256x768 -> 393216
#define OFF_GHH  655360     // 2 x 256x768 -> 393216
#define OFF_OUT  1048576    // 256x128  -> 32768
#define PACK_TOTAL 1081344

__device__ float g_pack[PACK_TOTAL];

__global__ void pack_kernel(const float* __restrict__ aw, const float* __restrict__ cw,
                            const float* __restrict__ gih, const float* __restrict__ ghh,
                            const float* __restrict__ ow)
{
    int i = blockIdx.x * blockDim.x + threadIdx.x;
    if (i >= PACK_TOTAL) return;
    float v;
    if (i < 131072) {                       // attn: K=512, N=256
        int c = i & 3, j = (i >> 2) & 255, k4 = i >> 10;
        v = aw[j * 512 + k4 * 4 + c];
    } else if (i < 262144) {                // comb: K=512, N=256
        int r = i - 131072;
        int c = r & 3, j = (r >> 2) & 255, k4 = r >> 10;
        v = cw[j * 512 + k4 * 4 + c];
    } else if (i < 655360) {                // gru ih: per layer K=256, N=768
        int r = i - 262144;
        int layer = r / 196608; int q = r % 196608;
        int c = q & 3; int t2 = q >> 2; int j = t2 % 768; int k4 = t2 / 768;
        v = gih[layer * 196608 + j * 256 + k4 * 4 + c];
    } else if (i < 1048576) {               // gru hh
        int r = i - 655360;
        int layer = r / 196608; int q = r % 196608;
        int c = q & 3; int t2 = q >> 2; int j = t2 % 768; int k4 = t2 / 768;
        v = ghh[layer * 196608 + j * 256 + k4 * 4 + c];
    } else {                                // out: K=256, N=128
        int r = i - 1048576;
        int c = r & 3, j = (r >> 2) & 127, k4 = r >> 9;
        v = ow[j * 256 + k4 * 4 + c];
    }
    g_pack[i] = v;
}

// ---------------- reductions ----------------
__device__ __forceinline__ float warp_reduce_sum(float v) {
    #pragma unroll
    for (int o = 16; o > 0; o >>= 1) v += __shfl_xor_sync(0xffffffffu, v, o);
    return v;
}
__device__ __forceinline__ float warp_reduce_max(float v) {
    #pragma unroll
    for (int o = 16; o > 0; o >>= 1) v = fmaxf(v, __shfl_xor_sync(0xffffffffu, v, o));
    return v;
}
// block (256 threads) reduce; 2 barriers, result broadcast to all threads
__device__ __forceinline__ float block_reduce_sum(float v, float* sm, int tid) {
    __syncthreads();
    v = warp_reduce_sum(v);
    if ((tid & 31) == 0) sm[tid >> 5] = v;
    __syncthreads();
    float r = sm[0];
    #pragma unroll
    for (int i = 1; i < 8; i++) r += sm[i];
    return r;
}
__device__ __forceinline__ float block_reduce_max(float v, float* sm, int tid) {
    __syncthreads();
    v = warp_reduce_max(v);
    if ((tid & 31) == 0) sm[tid >> 5] = v;
    __syncthreads();
    float r = sm[0];
    #pragma unroll
    for (int i = 1; i < 8; i++) r = fmaxf(r, sm[i]);
    return r;
}

// ---------------- main persistent decoder kernel ----------------
// grid = B/G = 128 CTAs, 256 threads. Each CTA owns 4 batch rows for all 64 steps.
__global__ __launch_bounds__(NTH)
void decoder_kernel(const float* __restrict__ x,      // [B,H,1,L]
                    const int*   __restrict__ y,      // [B,T]
                    const float* __restrict__ emb,    // [V,H]
                    const float* __restrict__ attn_b, // [L]
                    const float* __restrict__ comb_b, // [H]
                    const float* __restrict__ gbi,    // [2,768]
                    const float* __restrict__ gbh,    // [2,768]
                    const float* __restrict__ out_b,  // [V]
                    float* __restrict__ outp,         // [B,V,T]
                    float* __restrict__ attnp)        // [B,T,L]
{
    __shared__ __align__(16) float s_e  [G][Hh];
    __shared__ __align__(16) float s_h  [NL][G][Hh];
    __shared__ __align__(16) float s_aw [G][Ld];
    __shared__ __align__(16) float s_app[G][Hh];
    __shared__ __align__(16) float s_x  [G][Hh];
    __shared__ float s_red[8];

    const int tid  = threadIdx.x;
    const int wid  = tid >> 5;
    const int lane = tid & 31;
    const int b0   = blockIdx.x * G;

    const float* Pattn = g_pack + OFF_ATTN;
    const float* Pcomb = g_pack + OFF_COMB;
    const float* Pgih  = g_pack + OFF_GIH;
    const float* Pghh  = g_pack + OFF_GHH;
    const float* Pout  = g_pack + OFF_OUT;

    // init hidden to zero
    #pragma unroll
    for (int l = 0; l < NL; l++)
        #pragma unroll
        for (int g = 0; g < G; g++)
            s_h[l][g][tid] = 0.f;
    __syncthreads();

    for (int t = 0; t < Tt; t++) {
        // -------- embedding lookup (teacher forcing; SOS=0 at t=0) --------
        #pragma unroll
        for (int g = 0; g < G; g++) {
            int tok = (t == 0) ? 0 : y[(b0 + g) * Tt + t - 1];
            s_e[g][tid] = emb[tok * Hh + tid];
        }
        __syncthreads();

        // -------- attention scores: thread = l (output column) --------
        float sc[G];
        {
            const float bl = attn_b[tid];
            #pragma unroll
            for (int g = 0; g < G; g++) sc[g] = bl;
            const float4* P = (const float4*)Pattn + tid;
            #pragma unroll 4
            for (int k4 = 0; k4 < 64; k4++) {                 // k in [0,256): e
                float4 w = P[k4 * 256];
                #pragma unroll
                for (int g = 0; g < G; g++) {
                    float4 xv = ((const float4*)s_e[g])[k4];
                    sc[g] += w.x*xv.x + w.y*xv.y + w.z*xv.z + w.w*xv.w;
                }
            }
            #pragma unroll 4
            for (int k4 = 0; k4 < 64; k4++) {                 // k in [256,512): h0
                float4 w = P[(64 + k4) * 256];
                #pragma unroll
                for (int g = 0; g < G; g++) {
                    float4 xv = ((const float4*)s_h[0][g])[k4];
                    sc[g] += w.x*xv.x + w.y*xv.y + w.z*xv.z + w.w*xv.w;
                }
            }
        }

        // -------- softmax over L per row, write attns --------
        #pragma unroll
        for (int g = 0; g < G; g++) {
            float m = block_reduce_max(sc[g], s_red, tid);
            float p = __expf(sc[g] - m);
            float s = block_reduce_sum(p, s_red, tid);
            float a = p * (1.f / s);
            s_aw[g][tid] = a;
            attnp[((size_t)(b0 + g) * Tt + t) * Ld + tid] = a;
        }
        __syncthreads();

        // -------- applied = aw @ enc  (warp per (g,h) task, 4-way unrolled) --------
        {
            for (int it = 0; it < 32; it++) {
                int task0 = wid * 128 + it * 4;
                float d[4];
                #pragma unroll
                for (int u = 0; u < 4; u++) {
                    int task = task0 + u;
                    int g = task >> 8;
                    int h = task & 255;
                    const float4* xr = (const float4*)(x + ((size_t)(b0 + g) * Hh + h) * Ld);
                    const float4* ar = (const float4*)(s_aw[g]);
                    float4 x0 = xr[lane],    x1 = xr[lane + 32];
                    float4 a0 = ar[lane],    a1 = ar[lane + 32];
                    d[u] = x0.x*a0.x + x0.y*a0.y + x0.z*a0.z + x0.w*a0.w
                         + x1.x*a1.x + x1.y*a1.y + x1.z*a1.z + x1.w*a1.w;
                }
                #pragma unroll
                for (int u = 0; u < 4; u++) d[u] = warp_reduce_sum(d[u]);
                if (lane == 0) {
                    #pragma unroll
                    for (int u = 0; u < 4; u++) {
                        int task = task0 + u;
                        s_app[task >> 8][task & 255] = d[u];
                    }
                }
            }
        }
        __syncthreads();

        // -------- combine: g = relu([applied, e] @ comb_w^T + b) --------
        {
            const float bj = comb_b[tid];
            float cacc[G];
            #pragma unroll
            for (int g = 0; g < G; g++) cacc[g] = bj;
            const float4* P = (const float4*)Pcomb + tid;
            #pragma unroll 4
            for (int k4 = 0; k4 < 64; k4++) {                 // applied part
                float4 w = P[k4 * 256];
                #pragma unroll
                for (int g = 0; g < G; g++) {
                    float4 xv = ((const float4*)s_app[g])[k4];
                    cacc[g] += w.x*xv.x + w.y*xv.y + w.z*xv.z + w.w*xv.w;
                }
            }
            #pragma unroll 4
            for (int k4 = 0; k4 < 64; k4++) {                 // e part
                float4 w = P[(64 + k4) * 256];
                #pragma unroll
                for (int g = 0; g < G; g++) {
                    float4 xv = ((const float4*)s_e[g])[k4];
                    cacc[g] += w.x*xv.x + w.y*xv.y + w.z*xv.z + w.w*xv.w;
                }
            }
            __syncthreads();
            #pragma unroll
            for (int g = 0; g < G; g++) s_x[g][tid] = fmaxf(cacc[g], 0.f);
            __syncthreads();
        }

        // -------- GRU layers (thread owns hidden unit j = tid) --------
        #pragma unroll
        for (int l = 0; l < NL; l++) {
            float ai0[G], ai1[G], ai2[G], ah0[G], ah1[G], ah2[G];
            {
                float b0i = gbi[l * 768 + tid];
                float b1i = gbi[l * 768 + 256 + tid];
                float b2i = gbi[l * 768 + 512 + tid];
                float b0h = gbh[l * 768 + tid];
                float b1h = gbh[l * 768 + 256 + tid];
                float b2h = gbh[l * 768 + 512 + tid];
                #pragma unroll
                for (int g = 0; g < G; g++) {
                    ai0[g] = b0i; ai1[g] = b1i; ai2[g] = b2i;
                    ah0[g] = b0h; ah1[g] = b1h; ah2[g] = b2h;
                }
            }
            const float4* Pi = (const float4*)(Pgih + l * 196608);
            const float4* Ph = (const float4*)(Pghh + l * 196608);
            #pragma unroll 2
            for (int k4 = 0; k4 < 64; k4++) {
                float4 w0 = Pi[k4 * 768 + tid];
                float4 w1 = Pi[k4 * 768 + 256 + tid];
                float4 w2 = Pi[k4 * 768 + 512 + tid];
                #pragma unroll
                for (int g = 0; g < G; g++) {
                    float4 xv = ((const float4*)s_x[g])[k4];
                    ai0[g] += w0.x*xv.x + w0.y*xv.y + w0.z*xv.z + w0.w*xv.w;
                    ai1[g] += w1.x*xv.x + w1.y*xv.y + w1.z*xv.z + w1.w*xv.w;
                    ai2[g] += w2.x*xv.x + w2.y*xv.y + w2.z*xv.z + w2.w*xv.w;
                }
            }
            #pragma unroll 2
            for (int k4 = 0; k4 < 64; k4++) {
                float4 w0 = Ph[k4 * 768 + tid];
                float4 w1 = Ph[k4 * 768 + 256 + tid];
                float4 w2 = Ph[k4 * 768 + 512 + tid];
                #pragma unroll
                for (int g = 0; g < G; g++) {
                    float4 hv = ((const float4*)s_h[l][g])[k4];
                    ah0[g] += w0.x*hv.x + w0.y*hv.y + w0.z*hv.z + w0.w*hv.w;
                    ah1[g] += w1.x*hv.x + w1.y*hv.y + w1.z*hv.z + w1.w*hv.w;
                    ah2[g] += w2.x*hv.x + w2.y*hv.y + w2.z*hv.z + w2.w*hv.w;
                }
            }
            __syncthreads();
            #pragma unroll
            for (int g = 0; g < G; g++) {
                float r = 1.f / (1.f + __expf(-(ai0[g] + ah0[g])));
                float z = 1.f / (1.f + __expf(-(ai1[g] + ah1[g])));
                float n = tanhf(ai2[g] + r * ah2[g]);
                float hn = (1.f - z) * n + z * s_h[l][g][tid];
                s_h[l][g][tid] = hn;
                s_x[g][tid]    = hn;   // next layer / output input
            }
            __syncthreads();
        }

        // -------- output projection + log_softmax (thread pairs duplicate j) --------
        {
            int j = tid & 127;
            float oacc[G];
            const float bj = out_b[j];
            #pragma unroll
            for (int g = 0; g < G; g++) oacc[g] = bj;
            const float4* P = (const float4*)Pout + j;
            #pragma unroll 4
            for (int k4 = 0; k4 < 64; k4++) {
                float4 w = P[k4 * 128];
                #pragma unroll
                for (int g = 0; g < G; g++) {
                    float4 hv = ((const float4*)s_x[g])[k4];
                    oacc[g] += w.x*hv.x + w.y*hv.y + w.z*hv.z + w.w*hv.w;
                }
            }
            #pragma unroll
            for (int g = 0; g < G; g++) {
                float m = block_reduce_max(oacc[g], s_red, tid);        // duplicates OK for max
                float p = (tid < 128) ? __expf(oacc[g] - m) : 0.f;      // avoid double count
                float s = block_reduce_sum(p, s_red, tid);
                if (tid < 128) {
                    float lp = oacc[g] - m - logf(s);
                    outp[((size_t)(b0 + g) * Vv + j) * Tt + t] = lp;
                }
            }
        }
        __syncthreads();
    }
}

// ---------------- launch ----------------
extern "C" void kernel_launch(void* const* d_in, const int* in_sizes, int n_in,
                              void* d_out, int out_size)
{
    const float* x      = (const float*)d_in[0];
    const int*   y      = (const int*)  d_in[1];
    const float* emb    = (const float*)d_in[2];
    const float* attn_w = (const float*)d_in[3];
    const float* attn_b = (const float*)d_in[4];
    const float* comb_w = (const float*)d_in[5];
    const float* comb_b = (const float*)d_in[6];
    const float* gih    = (const float*)d_in[7];
    const float* ghh    = (const float*)d_in[8];
    const float* gbi    = (const float*)d_in[9];
    const float* gbh    = (const float*)d_in[10];
    const float* out_w  = (const float*)d_in[11];
    const float* out_b  = (const float*)d_in[12];

    float* outp  = (float*)d_out;                       // [B,V,T]
    float* attnp = (float*)d_out + (size_t)Bb * Vv * Tt; // [B,T,L]

    pack_kernel<<<(PACK_TOTAL + 255) / 256, 256>>>(attn_w, comb_w, gih, ghh, out_w);
    decoder_kernel<<<Bb / G, NTH>>>(x, y, emb, attn_b, comb_b, gbi, gbh, out_b, outp, attnp);
}

// round 2
// speedup vs baseline: 2.5555x; 2.5555x over previous
#include <cuda_runtime.h>
#include <math.h>

#define Bb   512
#define Hh   256
#define Ld   256
#define Tt   64
#define Vv   128
#define NL   2
#define G    4
#define NTH  512

// ---------------- packed weight scratch (transposed + k-interleaved) ----------------
// P[(k4*N + j)*4 + c] = W[j*K + 4*k4 + c] : thread owning output column j loads a
// float4 (=ulonglong2) of W[j][4k4..4k4+3], fully coalesced across a warp.
#define OFF_ATTN 0          // 512x256  -> 131072 floats
#define OFF_COMB 131072     // 512x256  -> 131072
#define OFF_GIH  262144     // 2 x 256x768 -> 393216
#define OFF_GHH  655360     // 2 x 256x768 -> 393216
#define OFF_OUT  1048576    // 256x128  -> 32768
#define PACK_TOTAL 1081344

__device__ __align__(16) float g_pack[PACK_TOTAL];

__global__ void pack_kernel(const float* __restrict__ aw, const float* __restrict__ cw,
                            const float* __restrict__ gih, const float* __restrict__ ghh,
                            const float* __restrict__ ow)
{
    int i = blockIdx.x * blockDim.x + threadIdx.x;
    if (i >= PACK_TOTAL) return;
    float v;
    if (i < 131072) {                       // attn: K=512, N=256
        int c = i & 3, j = (i >> 2) & 255, k4 = i >> 10;
        v = aw[j * 512 + k4 * 4 + c];
    } else if (i < 262144) {                // comb: K=512, N=256
        int r = i - 131072;
        int c = r & 3, j = (r >> 2) & 255, k4 = r >> 10;
        v = cw[j * 512 + k4 * 4 + c];
    } else if (i < 655360) {                // gru ih: per layer K=256, N=768
        int r = i - 262144;
        int layer = r / 196608; int q = r % 196608;
        int c = q & 3; int t2 = q >> 2; int j = t2 % 768; int k4 = t2 / 768;
        v = gih[layer * 196608 + j * 256 + k4 * 4 + c];
    } else if (i < 1048576) {               // gru hh
        int r = i - 655360;
        int layer = r / 196608; int q = r % 196608;
        int c = q & 3; int t2 = q >> 2; int j = t2 % 768; int k4 = t2 / 768;
        v = ghh[layer * 196608 + j * 256 + k4 * 4 + c];
    } else {                                // out: K=256, N=128
        int r = i - 1048576;
        int c = r & 3, j = (r >> 2) & 127, k4 = r >> 9;
        v = ow[j * 256 + k4 * 4 + c];
    }
    g_pack[i] = v;
}

// ---------------- f32x2 packed math helpers (sm_10x FFMA2) ----------------
typedef unsigned long long u64;

__device__ __forceinline__ void fma2(u64& d, u64 a, u64 b) {
    asm("fma.rn.f32x2 %0, %1, %2, %0;" : "+l"(d) : "l"(a), "l"(b));
}
__device__ __forceinline__ float sum2(u64 v) {
    float lo = __uint_as_float((unsigned)v);
    float hi = __uint_as_float((unsigned)(v >> 32));
    return lo + hi;
}

// ---------------- vectorized block reduction (4 values, 16 warps) ----------------
__device__ __forceinline__ void block_reduce4(float v[G], float* sm, int tid, bool is_max) {
    __syncthreads();                       // protect sm reuse
    #pragma unroll
    for (int g = 0; g < G; g++) {
        #pragma unroll
        for (int o = 16; o > 0; o >>= 1) {
            float oth = __shfl_xor_sync(0xffffffffu, v[g], o);
            v[g] = is_max ? fmaxf(v[g], oth) : (v[g] + oth);
        }
    }
    int wid = tid >> 5;
    if ((tid & 31) == 0) {
        #pragma unroll
        for (int g = 0; g < G; g++) sm[wid * G + g] = v[g];
    }
    __syncthreads();
    #pragma unroll
    for (int g = 0; g < G; g++) {
        float r = sm[g];
        #pragma unroll
        for (int w = 1; w < 16; w++)
            r = is_max ? fmaxf(r, sm[w * G + g]) : (r + sm[w * G + g]);
        v[g] = r;
    }
}

// ---------------- main persistent decoder kernel ----------------
// grid = 128 CTAs x 512 threads. Each CTA owns 4 batch rows for all 64 steps.
// Thread halves split every matvec: lo half (tid<256) = first K-half, hi half = second.
__global__ __launch_bounds__(NTH)
void decoder_kernel(const float* __restrict__ x,      // [B,H,1,L]
                    const int*   __restrict__ y,      // [B,T]
                    const float* __restrict__ emb,    // [V,H]
                    const float* __restrict__ attn_b, // [L]
                    const float* __restrict__ comb_b, // [H]
                    const float* __restrict__ gbi,    // [2,768]
                    const float* __restrict__ gbh,    // [2,768]
                    const float* __restrict__ out_b,  // [V]
                    float* __restrict__ outp,         // [B,V,T]
                    float* __restrict__ attnp)        // [B,T,L]
{
    __shared__ __align__(16) float s_e  [G][Hh];
    __shared__ __align__(16) float s_h  [NL][G][Hh];
    __shared__ __align__(16) float s_aw [G][Ld];
    __shared__ __align__(16) float s_app[G][Hh];
    __shared__ __align__(16) float s_x  [G][Hh];
    __shared__ __align__(16) float s_p2 [G][3][Hh];   // hi-half partials / out partials
    __shared__ float s_red[16 * G];

    const int tid  = threadIdx.x;
    const int wid  = tid >> 5;
    const int lane = tid & 31;
    const int jj   = tid & 255;
    const bool hi  = (tid >= 256);
    const int b0   = blockIdx.x * G;

    const float* Pattn = g_pack + OFF_ATTN;
    const float* Pcomb = g_pack + OFF_COMB;
    const float* Pgih  = g_pack + OFF_GIH;
    const float* Pghh  = g_pack + OFF_GHH;
    const float* Pout  = g_pack + OFF_OUT;

    // init hidden to zero
    for (int i = tid; i < NL * G * Hh; i += NTH)
        (&s_h[0][0][0])[i] = 0.f;
    __syncthreads();

    for (int t = 0; t < Tt; t++) {
        // -------- embedding lookup (teacher forcing; SOS=0 at t=0) --------
        #pragma unroll
        for (int i = tid; i < G * Hh; i += NTH) {
            int g = i >> 8, h = i & 255;
            int tok = (t == 0) ? 0 : y[(b0 + g) * Tt + t - 1];
            s_e[g][h] = emb[tok * Hh + h];
        }
        __syncthreads();

        // -------- attention scores: lo half does e-part, hi half does h-part --------
        {
            u64 acc[G] = {0, 0, 0, 0};
            const ulonglong2* W = (const ulonglong2*)Pattn + (hi ? 64 * 256 : 0) + jj;
            const float* vb = hi ? &s_h[0][0][0] : &s_e[0][0];
            #pragma unroll 4
            for (int k4 = 0; k4 < 64; k4++) {
                ulonglong2 w = W[k4 * 256];
                #pragma unroll
                for (int g = 0; g < G; g++) {
                    ulonglong2 xv = ((const ulonglong2*)(vb + g * Hh))[k4];
                    fma2(acc[g], w.x, xv.x);
                    fma2(acc[g], w.y, xv.y);
                }
            }
            if (hi) {
                #pragma unroll
                for (int g = 0; g < G; g++) s_p2[g][0][jj] = sum2(acc[g]);
            }
            __syncthreads();

            // -------- softmax over L per row (values live in lo half) --------
            float sc[G];
            #pragma unroll
            for (int g = 0; g < G; g++)
                sc[g] = hi ? -1e30f : (sum2(acc[g]) + s_p2[g][0][jj] + attn_b[jj]);
            float m[G];
            #pragma unroll
            for (int g = 0; g < G; g++) m[g] = sc[g];
            block_reduce4(m, s_red, tid, true);
            float p[G];
            #pragma unroll
            for (int g = 0; g < G; g++) p[g] = hi ? 0.f : __expf(sc[g] - m[g]);
            float s[G];
            #pragma unroll
            for (int g = 0; g < G; g++) s[g] = p[g];
            block_reduce4(s, s_red, tid, false);
            if (!hi) {
                #pragma unroll
                for (int g = 0; g < G; g++) {
                    float a = p[g] * (1.f / s[g]);
                    s_aw[g][jj] = a;
                    attnp[((size_t)(b0 + g) * Tt + t) * Ld + jj] = a;
                }
            }
            __syncthreads();
        }

        // -------- applied = aw @ enc  (16 warps x 64 tasks, 4-way unrolled) --------
        {
            for (int it = 0; it < 16; it++) {
                int task0 = wid * 64 + it * 4;
                float d[4];
                #pragma unroll
                for (int u = 0; u < 4; u++) {
                    int task = task0 + u;
                    int g = task >> 8, h = task & 255;
                    const ulonglong2* xr =
                        (const ulonglong2*)(x + ((size_t)(b0 + g) * Hh + h) * Ld);
                    const ulonglong2* ar = (const ulonglong2*)(s_aw[g]);
                    ulonglong2 x0 = xr[lane], x1 = xr[lane + 32];
                    ulonglong2 a0 = ar[lane], a1 = ar[lane + 32];
                    u64 acc = 0;
                    fma2(acc, x0.x, a0.x); fma2(acc, x0.y, a0.y);
                    fma2(acc, x1.x, a1.x); fma2(acc, x1.y, a1.y);
                    d[u] = sum2(acc);
                }
                #pragma unroll
                for (int u = 0; u < 4; u++) {
                    #pragma unroll
                    for (int o = 16; o > 0; o >>= 1)
                        d[u] += __shfl_xor_sync(0xffffffffu, d[u], o);
                }
                if (lane == 0) {
                    #pragma unroll
                    for (int u = 0; u < 4; u++) {
                        int task = task0 + u;
                        s_app[task >> 8][task & 255] = d[u];
                    }
                }
            }
        }
        __syncthreads();

        // -------- combine: lo half = applied-part, hi half = e-part --------
        {
            u64 acc[G] = {0, 0, 0, 0};
            const ulonglong2* W = (const ulonglong2*)Pcomb + (hi ? 64 * 256 : 0) + jj;
            const float* vb = hi ? &s_e[0][0] : &s_app[0][0];
            #pragma unroll 4
            for (int k4 = 0; k4 < 64; k4++) {
                ulonglong2 w = W[k4 * 256];
                #pragma unroll
                for (int g = 0; g < G; g++) {
                    ulonglong2 xv = ((const ulonglong2*)(vb + g * Hh))[k4];
                    fma2(acc[g], w.x, xv.x);
                    fma2(acc[g], w.y, xv.y);
                }
            }
            if (hi) {
                #pragma unroll
                for (int g = 0; g < G; g++) s_p2[g][0][jj] = sum2(acc[g]);
            }
            __syncthreads();
            if (!hi) {
                const float bj = comb_b[jj];
                #pragma unroll
                for (int g = 0; g < G; g++)
                    s_x[g][jj] = fmaxf(sum2(acc[g]) + s_p2[g][0][jj] + bj, 0.f);
            }
            __syncthreads();
        }

        // -------- GRU layers: lo half = ih matvec, hi half = hh matvec --------
        #pragma unroll
        for (int l = 0; l < NL; l++) {
            u64 a0[G] = {0,0,0,0}, a1[G] = {0,0,0,0}, a2[G] = {0,0,0,0};
            const ulonglong2* W =
                (const ulonglong2*)((hi ? Pghh : Pgih) + l * 196608) + jj;
            const float* vb = hi ? &s_h[l][0][0] : &s_x[0][0];
            #pragma unroll 2
            for (int k4 = 0; k4 < 64; k4++) {
                ulonglong2 w0 = W[k4 * 768];
                ulonglong2 w1 = W[k4 * 768 + 256];
                ulonglong2 w2 = W[k4 * 768 + 512];
                #pragma unroll
                for (int g = 0; g < G; g++) {
                    ulonglong2 xv = ((const ulonglong2*)(vb + g * Hh))[k4];
                    fma2(a0[g], w0.x, xv.x); fma2(a0[g], w0.y, xv.y);
                    fma2(a1[g], w1.x, xv.x); fma2(a1[g], w1.y, xv.y);
                    fma2(a2[g], w2.x, xv.x); fma2(a2[g], w2.y, xv.y);
                }
            }
            if (hi) {
                #pragma unroll
                for (int g = 0; g < G; g++) {
                    s_p2[g][0][jj] = sum2(a0[g]);
                    s_p2[g][1][jj] = sum2(a1[g]);
                    s_p2[g][2][jj] = sum2(a2[g]);
                }
            }
            __syncthreads();
            if (!hi) {
                const float bi0 = gbi[l * 768 + jj];
                const float bi1 = gbi[l * 768 + 256 + jj];
                const float bi2 = gbi[l * 768 + 512 + jj];
                const float bh0 = gbh[l * 768 + jj];
                const float bh1 = gbh[l * 768 + 256 + jj];
                const float bh2 = gbh[l * 768 + 512 + jj];
                #pragma unroll
                for (int g = 0; g < G; g++) {
                    float hprev = s_h[l][g][jj];
                    float i0 = sum2(a0[g]) + bi0, h0 = s_p2[g][0][jj] + bh0;
                    float i1 = sum2(a1[g]) + bi1, h1 = s_p2[g][1][jj] + bh1;
                    float i2 = sum2(a2[g]) + bi2, h2 = s_p2[g][2][jj] + bh2;
                    float r = 1.f / (1.f + __expf(-(i0 + h0)));
                    float z = 1.f / (1.f + __expf(-(i1 + h1)));
                    float n = tanhf(i2 + r * h2);
                    float hn = (1.f - z) * n + z * hprev;
                    s_h[l][g][jj] = hn;
                    s_x[g][jj]    = hn;
                }
            }
            __syncthreads();
        }

        // -------- output projection (K split 4 ways) + log_softmax --------
        {
            int j  = tid & 127;
            int sl = tid >> 7;               // 0..3, k4 slice [sl*16, sl*16+16)
            u64 acc[G] = {0, 0, 0, 0};
            const ulonglong2* W = (const ulonglong2*)Pout + j;
            #pragma unroll 4
            for (int k4 = sl * 16; k4 < sl * 16 + 16; k4++) {
                ulonglong2 w = W[k4 * 128];
                #pragma unroll
                for (int g = 0; g < G; g++) {
                    ulonglong2 hv = ((const ulonglong2*)s_x[g])[k4];
                    fma2(acc[g], w.x, hv.x);
                    fma2(acc[g], w.y, hv.y);
                }
            }
            float* s_op = &s_p2[0][0][0];     // alias: G*4*128 = 2048 <= 3072 floats
            #pragma unroll
            for (int g = 0; g < G; g++) s_op[(g * 4 + sl) * 128 + j] = sum2(acc[g]);
            __syncthreads();

            float oacc[G];
            #pragma unroll
            for (int g = 0; g < G; g++) {
                oacc[g] = (tid < 128)
                    ? (out_b[j] + s_op[(g * 4 + 0) * 128 + j] + s_op[(g * 4 + 1) * 128 + j]
                               + s_op[(g * 4 + 2) * 128 + j] + s_op[(g * 4 + 3) * 128 + j])
                    : -1e30f;
            }
            float m[G];
            #pragma unroll
            for (int g = 0; g < G; g++) m[g] = oacc[g];
            block_reduce4(m, s_red, tid, true);
            float p[G];
            #pragma unroll
            for (int g = 0; g < G; g++) p[g] = (tid < 128) ? __expf(oacc[g] - m[g]) : 0.f;
            float s[G];
            #pragma unroll
            for (int g = 0; g < G; g++) s[g] = p[g];
            block_reduce4(s, s_red, tid, false);
            if (tid < 128) {
                #pragma unroll
                for (int g = 0; g < G; g++) {
                    float lp = oacc[g] - m[g] - logf(s[g]);
                    outp[((size_t)(b0 + g) * Vv + j) * Tt + t] = lp;
                }
            }
        }
        __syncthreads();
    }
}

// ---------------- launch ----------------
extern "C" void kernel_launch(void* const* d_in, const int* in_sizes, int n_in,
                              void* d_out, int out_size)
{
    const float* x      = (const float*)d_in[0];
    const int*   y      = (const int*)  d_in[1];
    const float* emb    = (const float*)d_in[2];
    const float* attn_w = (const float*)d_in[3];
    const float* attn_b = (const float*)d_in[4];
    const float* comb_w = (const float*)d_in[5];
    const float* comb_b = (const float*)d_in[6];
    const float* gih    = (const float*)d_in[7];
    const float* ghh    = (const float*)d_in[8];
    const float* gbi    = (const float*)d_in[9];
    const float* gbh    = (const float*)d_in[10];
    const float* out_w  = (const float*)d_in[11];
    const float* out_b  = (const float*)d_in[12];

    float* outp  = (float*)d_out;                        // [B,V,T]
    float* attnp = (float*)d_out + (size_t)Bb * Vv * Tt; // [B,T,L]

    pack_kernel<<<(PACK_TOTAL + 255) / 256, 256>>>(attn_w, comb_w, gih, ghh, out_w);
    decoder_kernel<<<Bb / G, NTH>>>(x, y, emb, attn_b, comb_b, gbi, gbh, out_b, outp, attnp);
}

// round 4
// speedup vs baseline: 4.3490x; 1.7019x over previous
#include <cuda_runtime.h>
#include <cuda_fp16.h>
#include <math.h>

#define Bb   512
#define Hh   256
#define Ld   256
#define Tt   64
#define Vv   128
#define NL   2
#define G    4
#define NTH  512

// ---------------- packed weight scratch (transposed + k-interleaved) ----------------
#define OFF_ATTN 0          // 512x256  -> 131072 floats
#define OFF_COMB 131072     // 512x256  -> 131072
#define OFF_GIH  262144     // 2 x 256x768 -> 393216
#define OFF_GHH  655360     // 2 x 256x768 -> 393216
#define OFF_OUT  1048576    // 256x128  -> 32768
#define PACK_TOTAL 1081344

__device__ __align__(16) float  g_pack[PACK_TOTAL];
__device__ __align__(16) __half g_enc[(size_t)Bb * Hh * Ld];   // fp16 copy of encoder memory

__global__ void pack_kernel(const float* __restrict__ aw, const float* __restrict__ cw,
                            const float* __restrict__ gih, const float* __restrict__ ghh,
                            const float* __restrict__ ow)
{
    int i = blockIdx.x * blockDim.x + threadIdx.x;
    if (i >= PACK_TOTAL) return;
    float v;
    if (i < 131072) {                       // attn: K=512, N=256
        int c = i & 3, j = (i >> 2) & 255, k4 = i >> 10;
        v = aw[j * 512 + k4 * 4 + c];
    } else if (i < 262144) {                // comb: K=512, N=256
        int r = i - 131072;
        int c = r & 3, j = (r >> 2) & 255, k4 = r >> 10;
        v = cw[j * 512 + k4 * 4 + c];
    } else if (i < 655360) {                // gru ih: per layer K=256, N=768
        int r = i - 262144;
        int layer = r / 196608; int q = r % 196608;
        int c = q & 3; int t2 = q >> 2; int j = t2 % 768; int k4 = t2 / 768;
        v = gih[layer * 196608 + j * 256 + k4 * 4 + c];
    } else if (i < 1048576) {               // gru hh
        int r = i - 655360;
        int layer = r / 196608; int q = r % 196608;
        int c = q & 3; int t2 = q >> 2; int j = t2 % 768; int k4 = t2 / 768;
        v = ghh[layer * 196608 + j * 256 + k4 * 4 + c];
    } else {                                // out: K=256, N=128
        int r = i - 1048576;
        int c = r & 3, j = (r >> 2) & 127, k4 = r >> 9;
        v = ow[j * 256 + k4 * 4 + c];
    }
    g_pack[i] = v;
}

// fp32 -> fp16 encoder pack, vectorized (float4 in, uint2 out)
__global__ void pack_enc_kernel(const float* __restrict__ x)
{
    size_t i = (size_t)blockIdx.x * blockDim.x + threadIdx.x;   // i over float4s
    float4 v = ((const float4*)x)[i];
    __half2 h0 = __floats2half2_rn(v.x, v.y);
    __half2 h1 = __floats2half2_rn(v.z, v.w);
    uint2 o;
    o.x = *(unsigned*)&h0;
    o.y = *(unsigned*)&h1;
    ((uint2*)g_enc)[i] = o;
}

// ---------------- f32x2 packed math helpers (sm_10x FFMA2) ----------------
typedef unsigned long long u64;

__device__ __forceinline__ void fma2(u64& d, u64 a, u64 b) {
    asm("fma.rn.f32x2 %0, %1, %2, %0;" : "+l"(d) : "l"(a), "l"(b));
}
__device__ __forceinline__ float sum2(u64 v) {
    float lo = __uint_as_float((unsigned)v);
    float hi = __uint_as_float((unsigned)(v >> 32));
    return lo + hi;
}

// ---------------- vectorized block reduction (4 values, 16 warps) ----------------
__device__ __forceinline__ void block_reduce4(float v[G], float* sm, int tid, bool is_max) {
    __syncthreads();
    #pragma unroll
    for (int g = 0; g < G; g++) {
        #pragma unroll
        for (int o = 16; o > 0; o >>= 1) {
            float oth = __shfl_xor_sync(0xffffffffu, v[g], o);
            v[g] = is_max ? fmaxf(v[g], oth) : (v[g] + oth);
        }
    }
    int wid = tid >> 5;
    if ((tid & 31) == 0) {
        #pragma unroll
        for (int g = 0; g < G; g++) sm[wid * G + g] = v[g];
    }
    __syncthreads();
    #pragma unroll
    for (int g = 0; g < G; g++) {
        float r = sm[g];
        #pragma unroll
        for (int w = 1; w < 16; w++)
            r = is_max ? fmaxf(r, sm[w * G + g]) : (r + sm[w * G + g]);
        v[g] = r;
    }
}

// ---------------- main persistent decoder kernel ----------------
__global__ __launch_bounds__(NTH)
void decoder_kernel(const int*   __restrict__ y,      // [B,T]
                    const float* __restrict__ emb,    // [V,H]
                    const float* __restrict__ attn_b, // [L]
                    const float* __restrict__ comb_b, // [H]
                    const float* __restrict__ gbi,    // [2,768]
                    const float* __restrict__ gbh,    // [2,768]
                    const float* __restrict__ out_b,  // [V]
                    float* __restrict__ outp,         // [B,V,T]
                    float* __restrict__ attnp)        // [B,T,L]
{
    __shared__ __align__(16) float s_e  [G][Hh];
    __shared__ __align__(16) float s_h  [NL][G][Hh];
    __shared__ __align__(16) float s_aw [G][Ld];
    __shared__ __align__(16) float s_app[G][Hh];
    __shared__ __align__(16) float s_x  [G][Hh];
    __shared__ __align__(16) float s_p2 [G][3][Hh];   // hi-half partials / out partials
    __shared__ __align__(16) float s_out[G][Vv][8];   // output staging (8 steps)
    __shared__ float s_red[16 * G];

    const int tid  = threadIdx.x;
    const int wid  = tid >> 5;
    const int lane = tid & 31;
    const int jj   = tid & 255;
    const bool hi  = (tid >= 256);
    const int b0   = blockIdx.x * G;

    const float* Pattn = g_pack + OFF_ATTN;
    const float* Pcomb = g_pack + OFF_COMB;
    const float* Pgih  = g_pack + OFF_GIH;
    const float* Pghh  = g_pack + OFF_GHH;
    const float* Pout  = g_pack + OFF_OUT;

    for (int i = tid; i < NL * G * Hh; i += NTH)
        (&s_h[0][0][0])[i] = 0.f;
    __syncthreads();

    for (int t = 0; t < Tt; t++) {
        // -------- embedding lookup (teacher forcing; SOS=0 at t=0) --------
        #pragma unroll
        for (int i = tid; i < G * Hh; i += NTH) {
            int g = i >> 8, h = i & 255;
            int tok = (t == 0) ? 0 : y[(b0 + g) * Tt + t - 1];
            s_e[g][h] = emb[tok * Hh + h];
        }
        __syncthreads();

        // -------- attention scores: lo half = e-part, hi half = h-part --------
        {
            u64 acc[G] = {0, 0, 0, 0};
            const ulonglong2* W = (const ulonglong2*)Pattn + (hi ? 64 * 256 : 0) + jj;
            const float* vb = hi ? &s_h[0][0][0] : &s_e[0][0];
            #pragma unroll 4
            for (int k4 = 0; k4 < 64; k4++) {
                ulonglong2 w = W[k4 * 256];
                #pragma unroll
                for (int g = 0; g < G; g++) {
                    ulonglong2 xv = ((const ulonglong2*)(vb + g * Hh))[k4];
                    fma2(acc[g], w.x, xv.x);
                    fma2(acc[g], w.y, xv.y);
                }
            }
            if (hi) {
                #pragma unroll
                for (int g = 0; g < G; g++) s_p2[g][0][jj] = sum2(acc[g]);
            }
            __syncthreads();

            // softmax over L per row (true values live in lo half)
            float sc[G];
            #pragma unroll
            for (int g = 0; g < G; g++)
                sc[g] = hi ? -1e30f : (sum2(acc[g]) + s_p2[g][0][jj] + attn_b[jj]);
            float m[G];
            #pragma unroll
            for (int g = 0; g < G; g++) m[g] = sc[g];
            block_reduce4(m, s_red, tid, true);
            float p[G];
            #pragma unroll
            for (int g = 0; g < G; g++) p[g] = hi ? 0.f : __expf(sc[g] - m[g]);
            float s[G];
            #pragma unroll
            for (int g = 0; g < G; g++) s[g] = p[g];
            block_reduce4(s, s_red, tid, false);
            if (!hi) {
                #pragma unroll
                for (int g = 0; g < G; g++) {
                    float a = p[g] * (1.f / s[g]);
                    s_aw[g][jj] = a;
                    attnp[((size_t)(b0 + g) * Tt + t) * Ld + jj] = a;
                }
            }
            __syncthreads();
        }

        // -------- applied = aw @ enc (fp16 enc, warp owns fixed row g) --------
        {
            const int g = wid >> 2;                    // 4 warps per batch row
            const int hbase = (wid & 3) * 64;          // 64 h-values per warp
            const float4* awp = (const float4*)(s_aw[g]);
            const float4 A0 = awp[lane * 2];
            const float4 A1 = awp[lane * 2 + 1];
            const uint4* xrow =
                (const uint4*)(g_enc + ((size_t)(b0 + g) * Hh + hbase) * Ld) + lane;
            #pragma unroll
            for (int it = 0; it < 64; it += 8) {
                uint4 xv[8];
                #pragma unroll
                for (int u = 0; u < 8; u++) xv[u] = xrow[(it + u) * 32];
                float d[8];
                #pragma unroll
                for (int u = 0; u < 8; u++) {
                    float2 f0 = __half22float2(*(__half2*)&xv[u].x);
                    float2 f1 = __half22float2(*(__half2*)&xv[u].y);
                    float2 f2 = __half22float2(*(__half2*)&xv[u].z);
                    float2 f3 = __half22float2(*(__half2*)&xv[u].w);
                    d[u] = f0.x * A0.x + f0.y * A0.y + f1.x * A0.z + f1.y * A0.w
                         + f2.x * A1.x + f2.y * A1.y + f3.x * A1.z + f3.y * A1.w;
                }
                #pragma unroll
                for (int u = 0; u < 8; u++) {
                    #pragma unroll
                    for (int o = 16; o > 0; o >>= 1)
                        d[u] += __shfl_xor_sync(0xffffffffu, d[u], o);
                }
                if (lane == 0) {
                    #pragma unroll
                    for (int u = 0; u < 8; u++) s_app[g][hbase + it + u] = d[u];
                }
            }
        }
        __syncthreads();

        // -------- combine: lo half = applied-part, hi half = e-part --------
        {
            u64 acc[G] = {0, 0, 0, 0};
            const ulonglong2* W = (const ulonglong2*)Pcomb + (hi ? 64 * 256 : 0) + jj;
            const float* vb = hi ? &s_e[0][0] : &s_app[0][0];
            #pragma unroll 4
            for (int k4 = 0; k4 < 64; k4++) {
                ulonglong2 w = W[k4 * 256];
                #pragma unroll
                for (int g = 0; g < G; g++) {
                    ulonglong2 xv = ((const ulonglong2*)(vb + g * Hh))[k4];
                    fma2(acc[g], w.x, xv.x);
                    fma2(acc[g], w.y, xv.y);
                }
            }
            if (hi) {
                #pragma unroll
                for (int g = 0; g < G; g++) s_p2[g][0][jj] = sum2(acc[g]);
            }
            __syncthreads();
            if (!hi) {
                const float bj = comb_b[jj];
                #pragma unroll
                for (int g = 0; g < G; g++)
                    s_x[g][jj] = fmaxf(sum2(acc[g]) + s_p2[g][0][jj] + bj, 0.f);
            }
            __syncthreads();
        }

        // -------- GRU layers: lo half = ih matvec, hi half = hh matvec --------
        #pragma unroll
        for (int l = 0; l < NL; l++) {
            u64 a0[G] = {0,0,0,0}, a1[G] = {0,0,0,0}, a2[G] = {0,0,0,0};
            const ulonglong2* W =
                (const ulonglong2*)((hi ? Pghh : Pgih) + l * 196608) + jj;
            const float* vb = hi ? &s_h[l][0][0] : &s_x[0][0];
            #pragma unroll 2
            for (int k4 = 0; k4 < 64; k4++) {
                ulonglong2 w0 = W[k4 * 768];
                ulonglong2 w1 = W[k4 * 768 + 256];
                ulonglong2 w2 = W[k4 * 768 + 512];
                #pragma unroll
                for (int g = 0; g < G; g++) {
                    ulonglong2 xv = ((const ulonglong2*)(vb + g * Hh))[k4];
                    fma2(a0[g], w0.x, xv.x); fma2(a0[g], w0.y, xv.y);
                    fma2(a1[g], w1.x, xv.x); fma2(a1[g], w1.y, xv.y);
                    fma2(a2[g], w2.x, xv.x); fma2(a2[g], w2.y, xv.y);
                }
            }
            if (hi) {
                #pragma unroll
                for (int g = 0; g < G; g++) {
                    s_p2[g][0][jj] = sum2(a0[g]);
                    s_p2[g][1][jj] = sum2(a1[g]);
                    s_p2[g][2][jj] = sum2(a2[g]);
                }
            }
            __syncthreads();
            if (!hi) {
                const float bi0 = gbi[l * 768 + jj];
                const float bi1 = gbi[l * 768 + 256 + jj];
                const float bi2 = gbi[l * 768 + 512 + jj];
                const float bh0 = gbh[l * 768 + jj];
                const float bh1 = gbh[l * 768 + 256 + jj];
                const float bh2 = gbh[l * 768 + 512 + jj];
                #pragma unroll
                for (int g = 0; g < G; g++) {
                    float hprev = s_h[l][g][jj];
                    float i0 = sum2(a0[g]) + bi0, h0 = s_p2[g][0][jj] + bh0;
                    float i1 = sum2(a1[g]) + bi1, h1 = s_p2[g][1][jj] + bh1;
                    float i2 = sum2(a2[g]) + bi2, h2 = s_p2[g][2][jj] + bh2;
                    float r = 1.f / (1.f + __expf(-(i0 + h0)));
                    float z = 1.f / (1.f + __expf(-(i1 + h1)));
                    float n = tanhf(i2 + r * h2);
                    float hn = (1.f - z) * n + z * hprev;
                    s_h[l][g][jj] = hn;
                    s_x[g][jj]    = hn;
                }
            }
            __syncthreads();
        }

        // -------- output projection (K split 4 ways) + log_softmax --------
        {
            int j  = tid & 127;
            int sl = tid >> 7;
            u64 acc[G] = {0, 0, 0, 0};
            const ulonglong2* W = (const ulonglong2*)Pout + j;
            #pragma unroll 4
            for (int k4 = sl * 16; k4 < sl * 16 + 16; k4++) {
                ulonglong2 w = W[k4 * 128];
                #pragma unroll
                for (int g = 0; g < G; g++) {
                    ulonglong2 hv = ((const ulonglong2*)s_x[g])[k4];
                    fma2(acc[g], w.x, hv.x);
                    fma2(acc[g], w.y, hv.y);
                }
            }
            float* s_op = &s_p2[0][0][0];
            #pragma unroll
            for (int g = 0; g < G; g++) s_op[(g * 4 + sl) * 128 + j] = sum2(acc[g]);
            __syncthreads();

            float oacc[G];
            #pragma unroll
            for (int g = 0; g < G; g++) {
                oacc[g] = (tid < 128)
                    ? (out_b[j] + s_op[(g * 4 + 0) * 128 + j] + s_op[(g * 4 + 1) * 128 + j]
                               + s_op[(g * 4 + 2) * 128 + j] + s_op[(g * 4 + 3) * 128 + j])
                    : -1e30f;
            }
            float m[G];
            #pragma unroll
            for (int g = 0; g < G; g++) m[g] = oacc[g];
            block_reduce4(m, s_red, tid, true);
            float p[G];
            #pragma unroll
            for (int g = 0; g < G; g++) p[g] = (tid < 128) ? __expf(oacc[g] - m[g]) : 0.f;
            float s[G];
            #pragma unroll
            for (int g = 0; g < G; g++) s[g] = p[g];
            block_reduce4(s, s_red, tid, false);
            if (tid < 128) {
                #pragma unroll
                for (int g = 0; g < G; g++)
                    s_out[g][j][t & 7] = oacc[g] - m[g] - logf(s[g]);
            }
        }

        // -------- flush staged outputs every 8 steps (coalesced float4 x2) --------
        __syncthreads();
        if ((t & 7) == 7) {
            int g = tid >> 7, j = tid & 127;
            float4 v0 = *(float4*)&s_out[g][j][0];
            float4 v1 = *(float4*)&s_out[g][j][4];
            float4* dst = (float4*)(outp + ((size_t)(b0 + g) * Vv + j) * Tt + (t - 7));
            dst[0] = v0;
            dst[1] = v1;
            __syncthreads();
        }
    }
}

// ---------------- launch ----------------
extern "C" void kernel_launch(void* const* d_in, const int* in_sizes, int n_in,
                              void* d_out, int out_size)
{
    const float* x      = (const float*)d_in[0];
    const int*   y      = (const int*)  d_in[1];
    const float* emb    = (const float*)d_in[2];
    const float* attn_w = (const float*)d_in[3];
    const float* attn_b = (const float*)d_in[4];
    const float* comb_w = (const float*)d_in[5];
    const float* comb_b = (const float*)d_in[6];
    const float* gih    = (const float*)d_in[7];
    const float* ghh    = (const float*)d_in[8];
    const float* gbi    = (const float*)d_in[9];
    const float* gbh    = (const float*)d_in[10];
    const float* out_w  = (const float*)d_in[11];
    const float* out_b  = (const float*)d_in[12];

    float* outp  = (float*)d_out;                        // [B,V,T]
    float* attnp = (float*)d_out + (size_t)Bb * Vv * Tt; // [B,T,L]

    pack_kernel<<<(PACK_TOTAL + 255) / 256, 256>>>(attn_w, comb_w, gih, ghh, out_w);
    pack_enc_kernel<<<((size_t)Bb * Hh * Ld / 4 + 255) / 256, 256>>>(x);
    decoder_kernel<<<Bb / G, NTH>>>(y, emb, attn_b, comb_b, gbi, gbh, out_b, outp, attnp);
}